// round 5
// baseline (speedup 1.0000x reference)
#include <cuda_runtime.h>
#include <cuda_fp16.h>

#define FD    128          // feature dim D
#define NBRS  32           // neighbors per node M
#define ACOEF 0.9f         // residual mixing coefficient
#define MAXN  50001        // N + 1 pad row

typedef unsigned long long u64;

// Per-row precomputed: attention logit e_i = x_i @ att[D:], and an fp16 copy
// of x (256 B/row, 256B-aligned -> exactly 2 cache lines). Row N = zeros.
__device__ float g_e[MAXN];
__device__ __align__(256) uint4 g_xh[(size_t)MAXN * 16];

// ---- packed f32x2 helpers (FFMA2 is PTX-only; ptxas won't auto-fuse) ------
__device__ __forceinline__ u64 pk2(float lo, float hi) {
    u64 r; asm("mov.b64 %0, {%1, %2};" : "=l"(r) : "f"(lo), "f"(hi)); return r;
}
__device__ __forceinline__ void upk2(u64 v, float& lo, float& hi) {
    asm("mov.b64 {%0, %1}, %2;" : "=f"(lo), "=f"(hi) : "l"(v));
}
__device__ __forceinline__ u64 ffma2(u64 a, u64 b, u64 c) {
    u64 d; asm("fma.rn.f32x2 %0, %1, %2, %3;" : "=l"(d) : "l"(a), "l"(b), "l"(c));
    return d;
}
__device__ __forceinline__ u64 fadd2(u64 a, u64 b) {
    u64 d; asm("add.rn.f32x2 %0, %1, %2;" : "=l"(d) : "l"(a), "l"(b)); return d;
}
// half2 (as u32) -> packed f32x2 in a b64 pair
__device__ __forceinline__ u64 h2f2(unsigned h) {
    u64 r;
    asm("{\n\t.reg .b16 lo, hi;\n\t.reg .f32 flo, fhi;\n\t"
        "mov.b32 {lo, hi}, %1;\n\t"
        "cvt.f32.f16 flo, lo;\n\t"
        "cvt.f32.f16 fhi, hi;\n\t"
        "mov.b64 %0, {flo, fhi};\n\t}"
        : "=l"(r) : "r"(h));
    return r;
}

// ---------------------------------------------------------------------------
// Kernel 1: per-row precompute. One warp per row.
// ---------------------------------------------------------------------------
__global__ __launch_bounds__(256, 8)
void precompute_kernel(const float* __restrict__ x,
                       const float* __restrict__ att,
                       int N)
{
    const int row  = (blockIdx.x * blockDim.x + threadIdx.x) >> 5;
    const int lane = threadIdx.x & 31;
    if (row > N) return;

    float4 v = make_float4(0.f, 0.f, 0.f, 0.f);
    if (row < N) v = __ldg((const float4*)(x + (size_t)row * FD) + lane);
    const float4 a = __ldg((const float4*)(att + FD) + lane);

    float dot = fmaf(v.x, a.x, fmaf(v.y, a.y, fmaf(v.z, a.z, v.w * a.w)));
#pragma unroll
    for (int off = 16; off; off >>= 1)
        dot += __shfl_xor_sync(0xffffffffu, dot, off);
    if (lane == 0) g_e[row] = dot;

    __half2 h0 = __float22half2_rn(make_float2(v.x, v.y));
    __half2 h1 = __float22half2_rn(make_float2(v.z, v.w));
    uint2 packed;
    packed.x = *reinterpret_cast<unsigned*>(&h0);
    packed.y = *reinterpret_cast<unsigned*>(&h1);
    ((uint2*)g_xh)[(size_t)row * 32 + lane] = packed;
}

// ---------------------------------------------------------------------------
// Kernel 2: main routing. Half-warp per node. Within a half-warp: two 8-lane
// groups, each group loads one neighbor row per iteration; lane owns ONE full
// capsule (16 halves = 2 consecutive uint4). Capsule sum is lane-local ->
// no per-iteration shuffle on the critical path. Final xor-8 combine.
// ---------------------------------------------------------------------------
__global__ __launch_bounds__(256, 4)
void routing_kernel(const float* __restrict__ x,
                    const int*   __restrict__ nbr,
                    float*       __restrict__ out,
                    int N)
{
    const int lane = threadIdx.x & 31;
    const int l    = lane & 15;            // lane within half-warp
    const int g    = l >> 3;               // group: neighbor parity
    const int cap  = l & 7;                // capsule owned by this lane
    int n = blockIdx.x * 16 + (threadIdx.x >> 5) * 2 + (lane >> 4);
    if (n >= N) n = N - 1;                 // exact for N % 16 == 0

    // lane l holds neighbors m = 2l and 2l+1 (order irrelevant to the result)
    const int2  ii = __ldg((const int2*)(nbr + (size_t)n * NBRS) + l);
    const float e0 = __ldg(g_e + ii.x);
    const float e1 = __ldg(g_e + ii.y);

    // softmax over the 32 neighbors, within the 16-lane group
    float mx = fmaxf(e0, e1);
#pragma unroll
    for (int off = 8; off; off >>= 1)
        mx = fmaxf(mx, __shfl_xor_sync(0xffffffffu, mx, off, 16));
    const float p0 = __expf(e0 - mx);
    const float p1 = __expf(e1 - mx);
    float sum = p0 + p1;
#pragma unroll
    for (int off = 8; off; off >>= 1)
        sum += __shfl_xor_sync(0xffffffffu, sum, off, 16);
    const float inv  = ACOEF / sum;
    const float wgt0 = p0 * inv;
    const float wgt1 = p1 * inv;

    u64 acc[8] = {0, 0, 0, 0, 0, 0, 0, 0};   // 16 outputs: d = 16*cap .. +15

#pragma unroll
    for (int t = 0; t < NBRS / 2; ++t) {
        // neighbors 2t (group 0) and 2t+1 (group 1); both live in lane t
        const int   imx = __shfl_sync(0xffffffffu, ii.x, t, 16);
        const int   imy = __shfl_sync(0xffffffffu, ii.y, t, 16);
        const float wmx = __shfl_sync(0xffffffffu, wgt0, t, 16);
        const float wmy = __shfl_sync(0xffffffffu, wgt1, t, 16);
        const int   im  = g ? imy : imx;
        const float wm  = g ? wmy : wmx;

        const uint4* rp = &g_xh[(size_t)im * 16 + 2 * cap];
        const uint4 zp0 = __ldg(rp);
        const uint4 zp1 = __ldg(rp + 1);

        u64 z[8];
        z[0] = h2f2(zp0.x); z[1] = h2f2(zp0.y);
        z[2] = h2f2(zp0.z); z[3] = h2f2(zp0.w);
        z[4] = h2f2(zp1.x); z[5] = h2f2(zp1.y);
        z[6] = h2f2(zp1.z); z[7] = h2f2(zp1.w);

        // lane-local capsule sum (16 elements)
        const u64 s = fadd2(fadd2(fadd2(z[0], z[1]), fadd2(z[2], z[3])),
                            fadd2(fadd2(z[4], z[5]), fadd2(z[6], z[7])));
        float slo, shi; upk2(s, slo, shi);
        const float c  = wm * (slo + shi);
        const u64   cc = pk2(c, c);
#pragma unroll
        for (int j = 0; j < 8; ++j)
            acc[j] = ffma2(z[j], cc, acc[j]);
    }

    // combine the two 8-lane groups (they hit the same capsule outputs)
#pragma unroll
    for (int j = 0; j < 8; ++j) {
        float lo, hi; upk2(acc[j], lo, hi);
        lo += __shfl_xor_sync(0xffffffffu, lo, 8);
        hi += __shfl_xor_sync(0xffffffffu, hi, 8);
        acc[j] = pk2(lo, hi);
    }

    // store: group 0 writes d = 16cap..16cap+7, group 1 writes 16cap+8..+15
    {
        const int d0 = 16 * cap + 8 * g;   // first of this lane's 8 outputs
        float a0,a1,a2,a3,a4,a5,a6,a7;
        upk2(acc[4 * g + 0], a0, a1); upk2(acc[4 * g + 1], a2, a3);
        upk2(acc[4 * g + 2], a4, a5); upk2(acc[4 * g + 3], a6, a7);

        const float4* xr = (const float4*)(x + (size_t)n * FD + d0);
        const float4  x0 = __ldg(xr);
        const float4  x1 = __ldg(xr + 1);
        float4* orow = (float4*)(out + (size_t)n * FD + d0);
        orow[0] = make_float4(a0 + x0.x, a1 + x0.y, a2 + x0.z, a3 + x0.w);
        orow[1] = make_float4(a4 + x1.x, a5 + x1.y, a6 + x1.z, a7 + x1.w);
    }
}

extern "C" void kernel_launch(void* const* d_in, const int* in_sizes, int n_in,
                              void* d_out, int out_size)
{
    const float* x   = (const float*)d_in[0];   // (N, 128)
    const float* att = (const float*)d_in[1];   // (256, 1)
    const int*   nbr = (const int*)d_in[2];     // (N*32,)
    // d_in[3] = max_iter : provably unused (u never depends on routing var p)
    float* out = (float*)d_out;

    const int N = in_sizes[0] / FD;

    const int preBlocks  = (N + 1 + 7) / 8;     // rows 0..N (incl. pad record)
    precompute_kernel<<<preBlocks, 256>>>(x, att, N);

    const int mainBlocks = (N + 15) / 16;       // 16 nodes per 256-thread block
    routing_kernel<<<mainBlocks, 256>>>(x, nbr, out, N);
}

// round 6
// speedup vs baseline: 1.2281x; 1.2281x over previous
#include <cuda_runtime.h>
#include <cuda_fp16.h>

#define FD    128          // feature dim D
#define NBRS  32           // neighbors per node M
#define ACOEF 0.9f         // residual mixing coefficient
#define MAXN  50001        // N + 1 pad row

typedef unsigned long long u64;

// Per-row precomputed: attention logit e_i = x_i @ att[D:], and an fp16 copy
// of x (256 B/row, 256B-aligned -> exactly 2 cache lines). Row N = zeros.
__device__ float g_e[MAXN];
__device__ __align__(256) uint4 g_xh[(size_t)MAXN * 16];

// ---- packed f32x2 helpers (FFMA2 is PTX-only; ptxas won't auto-fuse) ------
__device__ __forceinline__ u64 pk2(float lo, float hi) {
    u64 r; asm("mov.b64 %0, {%1, %2};" : "=l"(r) : "f"(lo), "f"(hi)); return r;
}
__device__ __forceinline__ void upk2(u64 v, float& lo, float& hi) {
    asm("mov.b64 {%0, %1}, %2;" : "=f"(lo), "=f"(hi) : "l"(v));
}
__device__ __forceinline__ u64 ffma2(u64 a, u64 b, u64 c) {
    u64 d; asm("fma.rn.f32x2 %0, %1, %2, %3;" : "=l"(d) : "l"(a), "l"(b), "l"(c));
    return d;
}
__device__ __forceinline__ u64 fadd2(u64 a, u64 b) {
    u64 d; asm("add.rn.f32x2 %0, %1, %2;" : "=l"(d) : "l"(a), "l"(b)); return d;
}
// half2 (as u32) -> packed f32x2 in a b64 pair
__device__ __forceinline__ u64 h2f2(unsigned h) {
    u64 r;
    asm("{\n\t.reg .b16 lo, hi;\n\t.reg .f32 flo, fhi;\n\t"
        "mov.b32 {lo, hi}, %1;\n\t"
        "cvt.f32.f16 flo, lo;\n\t"
        "cvt.f32.f16 fhi, hi;\n\t"
        "mov.b64 %0, {flo, fhi};\n\t}"
        : "=l"(r) : "r"(h));
    return r;
}

// ---------------------------------------------------------------------------
// Kernel 1: per-row precompute. One warp per row.
// ---------------------------------------------------------------------------
__global__ __launch_bounds__(256, 8)
void precompute_kernel(const float* __restrict__ x,
                       const float* __restrict__ att,
                       int N)
{
    const int row  = (blockIdx.x * blockDim.x + threadIdx.x) >> 5;
    const int lane = threadIdx.x & 31;
    if (row > N) return;

    float4 v = make_float4(0.f, 0.f, 0.f, 0.f);
    if (row < N) v = __ldg((const float4*)(x + (size_t)row * FD) + lane);
    const float4 a = __ldg((const float4*)(att + FD) + lane);

    float dot = fmaf(v.x, a.x, fmaf(v.y, a.y, fmaf(v.z, a.z, v.w * a.w)));
#pragma unroll
    for (int off = 16; off; off >>= 1)
        dot += __shfl_xor_sync(0xffffffffu, dot, off);
    if (lane == 0) g_e[row] = dot;

    __half2 h0 = __float22half2_rn(make_float2(v.x, v.y));
    __half2 h1 = __float22half2_rn(make_float2(v.z, v.w));
    uint2 packed;
    packed.x = *reinterpret_cast<unsigned*>(&h0);
    packed.y = *reinterpret_cast<unsigned*>(&h1);
    ((uint2*)g_xh)[(size_t)row * 32 + lane] = packed;
}

// ---------------------------------------------------------------------------
// Kernel 2: main routing. HALF-WARP per node (R4 layout: 16 lanes load one
// 256-B row with a single LDG.128 each). Neighbors processed in blocks of 4
// with all 4 row loads issued back-to-back (explicit MLP=4) before any
// convert/FMA work consumes them.
// ---------------------------------------------------------------------------
__global__ __launch_bounds__(256, 5)
void routing_kernel(const float* __restrict__ x,
                    const int*   __restrict__ nbr,
                    float*       __restrict__ out,
                    int N)
{
    const int lane = threadIdx.x & 31;
    const int l    = lane & 15;            // lane within half-warp
    int n = blockIdx.x * 16 + (threadIdx.x >> 5) * 2 + (lane >> 4);
    if (n >= N) n = N - 1;                 // exact for N % 16 == 0

    // lane l holds neighbors m = 2l and 2l+1 (order irrelevant to the result)
    const int2  ii = __ldg((const int2*)(nbr + (size_t)n * NBRS) + l);
    const float e0 = __ldg(g_e + ii.x);
    const float e1 = __ldg(g_e + ii.y);

    // softmax over the 32 neighbors, within the 16-lane group
    float mx = fmaxf(e0, e1);
#pragma unroll
    for (int off = 8; off; off >>= 1)
        mx = fmaxf(mx, __shfl_xor_sync(0xffffffffu, mx, off, 16));
    const float p0 = __expf(e0 - mx);
    const float p1 = __expf(e1 - mx);
    float sum = p0 + p1;
#pragma unroll
    for (int off = 8; off; off >>= 1)
        sum += __shfl_xor_sync(0xffffffffu, sum, off, 16);
    const float inv  = ACOEF / sum;
    const float wgt0 = p0 * inv;
    const float wgt1 = p1 * inv;

    u64 acc0 = 0, acc1 = 0, acc2 = 0, acc3 = 0;   // f32x2 pairs

#pragma unroll
    for (int tb = 0; tb < NBRS / 4; ++tb) {
        // ---- issue 4 independent gathers back-to-back (MLP = 4) ----------
        uint4 zp[4];
        float wm[4];
#pragma unroll
        for (int j = 0; j < 4; ++j) {
            const int t  = tb * 4 + j;     // compile-time constant
            const int im = __shfl_sync(0xffffffffu,
                                       (t & 1) ? ii.y : ii.x, t >> 1, 16);
            wm[j] = __shfl_sync(0xffffffffu,
                                (t & 1) ? wgt1 : wgt0, t >> 1, 16);
            zp[j] = __ldg(&g_xh[(size_t)im * 16 + l]);
        }
        // ---- consume the 4 rows ------------------------------------------
#pragma unroll
        for (int j = 0; j < 4; ++j) {
            const u64 z0 = h2f2(zp[j].x);
            const u64 z1 = h2f2(zp[j].y);
            const u64 z2 = h2f2(zp[j].z);
            const u64 z3 = h2f2(zp[j].w);

            // capsule sum: this lane's 8 elems + pair lane's 8 (capsule = 16)
            const u64 s = fadd2(fadd2(z0, z1), fadd2(z2, z3));
            float slo, shi; upk2(s, slo, shi);
            float cs = slo + shi;
            cs += __shfl_xor_sync(0xffffffffu, cs, 1);

            const float c  = wm[j] * cs;
            const u64   cc = pk2(c, c);
            acc0 = ffma2(z0, cc, acc0);
            acc1 = ffma2(z1, cc, acc1);
            acc2 = ffma2(z2, cc, acc2);
            acc3 = ffma2(z3, cc, acc3);
        }
    }

    // combine the two half-warp parity groups? Not needed: each half-warp
    // iterated over ALL 32 neighbors of its own node. Unpack + residual.
    float a0,a1,a2,a3,a4,a5,a6,a7;
    upk2(acc0, a0, a1); upk2(acc1, a2, a3);
    upk2(acc2, a4, a5); upk2(acc3, a6, a7);

    const float4* xr = (const float4*)(x + (size_t)n * FD);
    const float4  x0 = __ldg(xr + 2 * l);
    const float4  x1 = __ldg(xr + 2 * l + 1);
    float4* orow = (float4*)(out + (size_t)n * FD);
    orow[2 * l]     = make_float4(a0 + x0.x, a1 + x0.y, a2 + x0.z, a3 + x0.w);
    orow[2 * l + 1] = make_float4(a4 + x1.x, a5 + x1.y, a6 + x1.z, a7 + x1.w);
}

extern "C" void kernel_launch(void* const* d_in, const int* in_sizes, int n_in,
                              void* d_out, int out_size)
{
    const float* x   = (const float*)d_in[0];   // (N, 128)
    const float* att = (const float*)d_in[1];   // (256, 1)
    const int*   nbr = (const int*)d_in[2];     // (N*32,)
    // d_in[3] = max_iter : provably unused (u never depends on routing var p)
    float* out = (float*)d_out;

    const int N = in_sizes[0] / FD;

    const int preBlocks  = (N + 1 + 7) / 8;     // rows 0..N (incl. pad record)
    precompute_kernel<<<preBlocks, 256>>>(x, att, N);

    const int mainBlocks = (N + 15) / 16;       // 16 nodes per 256-thread block
    routing_kernel<<<mainBlocks, 256>>>(x, nbr, out, N);
}